// round 6
// baseline (speedup 1.0000x reference)
#include <cuda_runtime.h>
#include <cuda_bf16.h>
#include <cstdint>

// Problem constants (fixed-shape problem)
#define NNODES 50000
#define NEDGES 800000
#define NF     128
#define EF     32
#define HID    300
#define MSGD   128
#define NHID   128
#define NGRAPH 64

// Edge pipeline chunking: keeps total __device__ scratch < 2GB (host-side
// shadow vars of __device__ globals live in .bss; >2GB breaks GOTPCREL
// relocation against static cudart at link time).
#define ECHUNK 200000
#define NCHUNK (NEDGES / ECHUNK)

// ---------------------------------------------------------------------------
// Scratch: __device__ globals (cudaMalloc is forbidden). Total ~830 MB.
// ---------------------------------------------------------------------------
__device__ float g_Pa[NNODES * HID];            // x @ W1[0:128] + b1   (dst proj)
__device__ float g_Pb[NNODES * HID];            // x @ W1[128:256]      (src proj)
__device__ float g_h1[(size_t)ECHUNK * HID];    // edge hidden 1 (chunk)
__device__ float g_h2[(size_t)ECHUNK * HID];    // edge hidden 2 (chunk)
__device__ float g_aggr[NNODES * MSGD];         // segment-summed messages
__device__ float g_u[NNODES * (NF + MSGD)];     // [x, aggr]
__device__ float g_n1[NNODES * HID];
__device__ float g_n2[NNODES * HID];
__device__ float g_hn[NNODES * NHID];           // per-node output
__device__ float g_pool[NGRAPH * NHID];
__device__ float g_cnt[NGRAPH];
__device__ int   g_src[NEDGES];
__device__ int   g_dst[NEDGES];
__device__ int   g_batch[NNODES];
__device__ int   g_e64;   // edge_index is int64?
__device__ int   g_b64;   // batch is int64?

// ---------------------------------------------------------------------------
// dtype detection: int64 little-endian high words are 0 for values < 2^31.
// batch is SORTED (early values legitimately 0) -> sample odd words near END.
// edge_index values are uniform random -> sample first odd words.
// ---------------------------------------------------------------------------
__global__ void detect_k(const int* __restrict__ e, const int* __restrict__ b,
                         int nn) {
    __shared__ int se, sb;
    int t = threadIdx.x;
    if (t == 0) { se = 1; sb = 1; }
    __syncthreads();
    if (e[2 * t + 1] != 0) se = 0;          // word idx <= 127 < 1.6M (safe either way)
    int w = nn - 1 - 2 * t;                 // odd, within [0, nn)
    if (b[w] != 0) sb = 0;
    __syncthreads();
    if (t == 0) { g_e64 = se; g_b64 = sb; }
}

__global__ void convert_k(const int* __restrict__ e, const int* __restrict__ b,
                          int ne, int nn) {
    int i = blockIdx.x * blockDim.x + threadIdx.x;
    int e64 = g_e64, b64 = g_b64;
    if (i < ne) {
        if (e64) { g_src[i] = e[2 * i];      g_dst[i] = e[2 * (ne + i)]; }
        else     { g_src[i] = e[i];          g_dst[i] = e[ne + i]; }
    }
    if (i < nn) g_batch[i] = b64 ? b[2 * i] : b[i];
}

__global__ void zero_k() {
    long i = blockIdx.x * (long)blockDim.x + threadIdx.x;
    long stride = gridDim.x * (long)blockDim.x;
    for (long j = i; j < (long)NNODES * MSGD; j += stride) g_aggr[j] = 0.0f;
    if (i < NGRAPH * NHID) g_pool[i] = 0.0f;
    if (i < NGRAPH) g_cnt[i] = 0.0f;
}

// ---------------------------------------------------------------------------
// Generic SGEMM: C[M,N] = epilogue(A[M,K] @ B[K,N])
// BM=BN=128, BK=16, 256 threads, 8x8 per-thread tile, 2-stage smem pipeline.
// MODE 0: C = (relu?)(acc + bias), store (float4)
// MODE 1: C = relu(acc + Pa[dst[row]] + Pb[src[row]]), store      (edge layer1)
// MODE 2: atomicAdd(C[dst[row]*ldc + col], acc + bias)            (edge layer3)
// All K, N, ld used are multiples of 4 -> float4 guards at 4-elem granularity.
// ---------------------------------------------------------------------------
#define BM 128
#define BN 128
#define BK 16
#define TM 8
#define TN 8

template <int MODE>
__global__ void __launch_bounds__(256, 2)
sgemm_k(int M, int N, int K,
        const float* __restrict__ A, int lda,
        const float* __restrict__ B, int ldb,
        const float* __restrict__ bias,
        float* __restrict__ C, int ldc,
        int relu,
        const int* __restrict__ rdst, const int* __restrict__ rsrc,
        const float* __restrict__ Pa, const float* __restrict__ Pb, int ldp) {
    __shared__ float As[2][BK * BM];   // transposed: As[k][m]
    __shared__ float Bs[2][BK * BN];

    const int row0 = blockIdx.x * BM;
    const int col0 = blockIdx.y * BN;
    const int tid = threadIdx.x;
    const int tr = tid / (BN / TN);   // 0..15
    const int tc = tid % (BN / TN);   // 0..15

    const int aRow  = tid / (BK / 4); // 0..63
    const int aCol4 = tid % (BK / 4); // 0..3
    const int bRow  = tid / (BN / 4); // 0..7
    const int bCol4 = tid % (BN / 4); // 0..31

    float acc[TM][TN];
#pragma unroll
    for (int i = 0; i < TM; i++)
#pragma unroll
        for (int j = 0; j < TN; j++) acc[i][j] = 0.0f;

    float4 va[2], vb[2];

    auto ldg = [&](int k0) {
#pragma unroll
        for (int r = 0; r < 2; r++) {
            int grow = row0 + aRow + r * 64;
            int gk = k0 + aCol4 * 4;
            va[r] = make_float4(0.f, 0.f, 0.f, 0.f);
            if (grow < M && gk < K)
                va[r] = *(const float4*)(A + (size_t)grow * lda + gk);
        }
#pragma unroll
        for (int r = 0; r < 2; r++) {
            int gk = k0 + bRow + r * 8;
            int gcol = col0 + bCol4 * 4;
            vb[r] = make_float4(0.f, 0.f, 0.f, 0.f);
            if (gk < K && gcol < N)
                vb[r] = *(const float4*)(B + (size_t)gk * ldb + gcol);
        }
    };

    auto sts = [&](int buf) {
#pragma unroll
        for (int r = 0; r < 2; r++) {
            As[buf][(aCol4 * 4 + 0) * BM + aRow + r * 64] = va[r].x;
            As[buf][(aCol4 * 4 + 1) * BM + aRow + r * 64] = va[r].y;
            As[buf][(aCol4 * 4 + 2) * BM + aRow + r * 64] = va[r].z;
            As[buf][(aCol4 * 4 + 3) * BM + aRow + r * 64] = va[r].w;
        }
#pragma unroll
        for (int r = 0; r < 2; r++)
            *(float4*)(&Bs[buf][(bRow + r * 8) * BN + bCol4 * 4]) = vb[r];
    };

    const int nst = (K + BK - 1) / BK;
    ldg(0);
    sts(0);
    __syncthreads();

    for (int s = 0; s < nst; s++) {
        const int buf = s & 1;
        if (s + 1 < nst) ldg((s + 1) * BK);   // prefetch next stage into regs
#pragma unroll
        for (int kk = 0; kk < BK; kk++) {
            float ra[TM], rb[TN];
#pragma unroll
            for (int i = 0; i < TM; i++) ra[i] = As[buf][kk * BM + tr * TM + i];
#pragma unroll
            for (int j = 0; j < TN; j++) rb[j] = Bs[buf][kk * BN + tc * TN + j];
#pragma unroll
            for (int i = 0; i < TM; i++)
#pragma unroll
                for (int j = 0; j < TN; j++) acc[i][j] += ra[i] * rb[j];
        }
        if (s + 1 < nst) {
            sts(buf ^ 1);
            __syncthreads();
        }
    }

    // epilogue (all cols are 4-aligned; N multiple of 4 -> float4-safe)
#pragma unroll
    for (int i = 0; i < TM; i++) {
        int row = row0 + tr * TM + i;
        if (row >= M) continue;
        int dn = 0, sn = 0;
        if (MODE == 1) { dn = rdst[row]; sn = rsrc[row]; }
        if (MODE == 2) { dn = rdst[row]; }
#pragma unroll
        for (int j = 0; j < TN; j += 4) {
            int col = col0 + tc * TN + j;
            if (col >= N) continue;
            float4 v = make_float4(acc[i][j], acc[i][j + 1],
                                   acc[i][j + 2], acc[i][j + 3]);
            if (bias) {
                float4 bb = *(const float4*)(bias + col);
                v.x += bb.x; v.y += bb.y; v.z += bb.z; v.w += bb.w;
            }
            if (MODE == 0) {
                if (relu) {
                    v.x = fmaxf(v.x, 0.f); v.y = fmaxf(v.y, 0.f);
                    v.z = fmaxf(v.z, 0.f); v.w = fmaxf(v.w, 0.f);
                }
                *(float4*)(C + (size_t)row * ldc + col) = v;
            } else if (MODE == 1) {
                float4 a4 = *(const float4*)(Pa + (size_t)dn * ldp + col);
                float4 b4 = *(const float4*)(Pb + (size_t)sn * ldp + col);
                v.x = fmaxf(v.x + a4.x + b4.x, 0.f);
                v.y = fmaxf(v.y + a4.y + b4.y, 0.f);
                v.z = fmaxf(v.z + a4.z + b4.z, 0.f);
                v.w = fmaxf(v.w + a4.w + b4.w, 0.f);
                *(float4*)(C + (size_t)row * ldc + col) = v;
            } else {
                float* p = C + (size_t)dn * ldc + col;
                atomicAdd(p + 0, v.x);
                atomicAdd(p + 1, v.y);
                atomicAdd(p + 2, v.z);
                atomicAdd(p + 3, v.w);
            }
        }
    }
}

// ---------------------------------------------------------------------------
// concat u = [x, aggr]
// ---------------------------------------------------------------------------
__global__ void concat_k(const float* __restrict__ x, int nn) {
    int idx = blockIdx.x * blockDim.x + threadIdx.x;
    int n = idx >> 8, c = idx & 255;
    if (n < nn)
        g_u[idx] = (c < NF) ? x[n * NF + c] : g_aggr[n * MSGD + (c - NF)];
}

// ---------------------------------------------------------------------------
// pool: segment-sum per graph + counts
// ---------------------------------------------------------------------------
__global__ void pool_k(const float* __restrict__ h, int nn) {
    int idx = blockIdx.x * blockDim.x + threadIdx.x;
    int n = idx >> 7, c = idx & 127;
    if (n < nn) {
        int b = g_batch[n];
        atomicAdd(&g_pool[b * NHID + c], h[idx]);
        if (c == 0) atomicAdd(&g_cnt[b], 1.0f);
    }
}

// ---------------------------------------------------------------------------
// global MLP: one block per graph, 128 threads. pooled = pool/max(cnt,1);
// out = mlp3(pooled)
// ---------------------------------------------------------------------------
__global__ void gmlp_k(const float* __restrict__ W1, const float* __restrict__ b1,
                       const float* __restrict__ W2, const float* __restrict__ b2,
                       const float* __restrict__ W3, const float* __restrict__ b3,
                       float* __restrict__ out) {
    int g = blockIdx.x, t = threadIdx.x;
    __shared__ float s_in[NHID], s_h[NHID];
    float c = fmaxf(g_cnt[g], 1.0f);
    s_in[t] = g_pool[g * NHID + t] / c;
    __syncthreads();
    float a = b1[t];
    for (int k = 0; k < NHID; k++) a += s_in[k] * W1[k * NHID + t];
    s_h[t] = fmaxf(a, 0.0f);
    __syncthreads();
    a = b2[t];
    for (int k = 0; k < NHID; k++) a += s_h[k] * W2[k * NHID + t];
    a = fmaxf(a, 0.0f);
    __syncthreads();
    s_in[t] = a * W3[t];           // W3 is [128,1]
    __syncthreads();
    for (int s = 64; s > 0; s >>= 1) {
        if (t < s) s_in[t] += s_in[t + s];
        __syncthreads();
    }
    if (t == 0) out[g] = s_in[0] + b3[0];
}

// ---------------------------------------------------------------------------
// launch
// ---------------------------------------------------------------------------
static dim3 gemm_grid(int M, int N) {
    return dim3((M + BM - 1) / BM, (N + BN - 1) / BN);
}

extern "C" void kernel_launch(void* const* d_in, const int* in_sizes, int n_in,
                              void* d_out, int out_size) {
    const float* x       = (const float*)d_in[0];
    const int*   eidx    = (const int*)d_in[1];   // int32 or int64, detected
    const float* eattr   = (const float*)d_in[2];
    const int*   batch   = (const int*)d_in[3];
    const float* msg_W1  = (const float*)d_in[4];
    const float* msg_b1  = (const float*)d_in[5];
    const float* msg_W2  = (const float*)d_in[6];
    const float* msg_b2  = (const float*)d_in[7];
    const float* msg_W3  = (const float*)d_in[8];
    const float* msg_b3  = (const float*)d_in[9];
    const float* node_W1 = (const float*)d_in[10];
    const float* node_b1 = (const float*)d_in[11];
    const float* node_W2 = (const float*)d_in[12];
    const float* node_b2 = (const float*)d_in[13];
    const float* node_W3 = (const float*)d_in[14];
    const float* node_b3 = (const float*)d_in[15];
    const float* glob_W1 = (const float*)d_in[16];
    const float* glob_b1 = (const float*)d_in[17];
    const float* glob_W2 = (const float*)d_in[18];
    const float* glob_b2 = (const float*)d_in[19];
    const float* glob_W3 = (const float*)d_in[20];
    const float* glob_b3 = (const float*)d_in[21];
    float* out = (float*)d_out;

    // scratch addresses
    float *pPa, *pPb, *ph1, *ph2, *pag, *pu, *pn1, *pn2, *phn;
    int *psrc, *pdst;
    cudaGetSymbolAddress((void**)&pPa, g_Pa);
    cudaGetSymbolAddress((void**)&pPb, g_Pb);
    cudaGetSymbolAddress((void**)&ph1, g_h1);
    cudaGetSymbolAddress((void**)&ph2, g_h2);
    cudaGetSymbolAddress((void**)&pag, g_aggr);
    cudaGetSymbolAddress((void**)&pu, g_u);
    cudaGetSymbolAddress((void**)&pn1, g_n1);
    cudaGetSymbolAddress((void**)&pn2, g_n2);
    cudaGetSymbolAddress((void**)&phn, g_hn);
    cudaGetSymbolAddress((void**)&psrc, g_src);
    cudaGetSymbolAddress((void**)&pdst, g_dst);

    const int NE = NEDGES, NN = NNODES;

    // 0. dtype detection + index normalization + zero accumulators
    detect_k<<<1, 64>>>(eidx, batch, NN);
    convert_k<<<(NE + 255) / 256, 256>>>(eidx, batch, NE, NN);
    zero_k<<<4096, 256>>>();

    // 1. node projections: Pa = x @ W1[0:128] + b1 ; Pb = x @ W1[128:256]
    sgemm_k<0><<<gemm_grid(NN, HID), 256>>>(NN, HID, NF, x, NF,
        msg_W1, HID, msg_b1, pPa, HID, 0, nullptr, nullptr, nullptr, nullptr, 0);
    sgemm_k<0><<<gemm_grid(NN, HID), 256>>>(NN, HID, NF, x, NF,
        msg_W1 + (size_t)NF * HID, HID, nullptr, pPb, HID, 0,
        nullptr, nullptr, nullptr, nullptr, 0);

    // 2-4. edge pipeline, chunked (keeps scratch < 2GB for the host linker)
    for (int c = 0; c < NCHUNK; c++) {
        const int e0 = c * ECHUNK;
        const int Mc = ECHUNK;

        // edge layer 1: h1 = relu(eattr @ W1c + Pa[dst] + Pb[src])
        sgemm_k<1><<<gemm_grid(Mc, HID), 256>>>(Mc, HID, EF,
            eattr + (size_t)e0 * EF, EF,
            msg_W1 + (size_t)(2 * NF) * HID, HID, nullptr, ph1, HID, 1,
            pdst + e0, psrc + e0, pPa, pPb, HID);

        // edge layer 2: h2 = relu(h1 @ W2 + b2)   (the big GEMM)
        sgemm_k<0><<<gemm_grid(Mc, HID), 256>>>(Mc, HID, HID, ph1, HID,
            msg_W2, HID, msg_b2, ph2, HID, 1,
            nullptr, nullptr, nullptr, nullptr, 0);

        // edge layer 3 + scatter: aggr[dst] += h2 @ W3 + b3
        sgemm_k<2><<<gemm_grid(Mc, MSGD), 256>>>(Mc, MSGD, HID, ph2, HID,
            msg_W3, MSGD, msg_b3, pag, MSGD, 0,
            pdst + e0, nullptr, nullptr, nullptr, 0);
    }

    // 5. node MLP on [x, aggr]
    concat_k<<<(NN * 256 + 255) / 256, 256>>>(x, NN);
    sgemm_k<0><<<gemm_grid(NN, HID), 256>>>(NN, HID, NF + MSGD, pu, NF + MSGD,
        node_W1, HID, node_b1, pn1, HID, 1, nullptr, nullptr, nullptr, nullptr, 0);
    sgemm_k<0><<<gemm_grid(NN, HID), 256>>>(NN, HID, HID, pn1, HID,
        node_W2, HID, node_b2, pn2, HID, 1, nullptr, nullptr, nullptr, nullptr, 0);
    sgemm_k<0><<<gemm_grid(NN, NHID), 256>>>(NN, NHID, HID, pn2, HID,
        node_W3, NHID, node_b3, phn, NHID, 0, nullptr, nullptr, nullptr, nullptr, 0);

    // 6. mean pool per graph + global MLP
    pool_k<<<(NN * NHID + 255) / 256, 256>>>(phn, NN);
    gmlp_k<<<NGRAPH, NHID>>>(glob_W1, glob_b1, glob_W2, glob_b2,
                             glob_W3, glob_b3, out);
}